// round 3
// baseline (speedup 1.0000x reference)
#include <cuda_runtime.h>

#define NQ   10
#define DIM  1024
#define NL   4
#define NOUT 16
#define TPB  256

// Scratch (allocation-free rule: __device__ globals)
__device__ float          g_gates[NL * NQ * 8];   // 40 gates x {ar,ai,br,bi,cr,ci,dr,di}
__device__ unsigned short g_perm[NL][DIM];        // per-layer CNOT-block basis permutation

// ---------------------------------------------------------------------------
// Init kernel: build gate matrices + CNOT-layer permutation tables.
// Qubit q <-> bit position (NQ-1-q)  (qubit 0 is MSB in the reference).
// Layer perm: state_new[j] = state_old[ sigma_0(sigma_1(...sigma_9(j)...)) ]
// where sigma_q toggles target bit iff control bit of the *current* index set.
// ---------------------------------------------------------------------------
__global__ void vqc_init(const float* __restrict__ wts) {
    int l = blockIdx.x;                 // 0..NL-1
    int r = l % (NQ - 1) + 1;
    for (int j = threadIdx.x; j < DIM; j += blockDim.x) {
        int t = j;
        #pragma unroll
        for (int q = NQ - 1; q >= 0; --q) {
            int pc = NQ - 1 - q;
            int pt = NQ - 1 - ((q + r) % NQ);
            t ^= ((t >> pc) & 1) << pt;
        }
        g_perm[l][j] = (unsigned short)t;
    }
    if (l == 0 && threadIdx.x < NL * NQ) {
        int idx   = threadIdx.x;
        float phi = wts[idx * 3 + 0];
        float th  = wts[idx * 3 + 1];
        float om  = wts[idx * 3 + 2];
        float sh, ch;  sincosf(0.5f * th, &sh, &ch);
        float ssp, csp; sincosf(0.5f * (phi + om), &ssp, &csp);
        float ssm, csm; sincosf(0.5f * (phi - om), &ssm, &csm);
        float* g = &g_gates[idx * 8];
        g[0] =  csp * ch;  g[1] = -ssp * ch;   // a  = e^{-i(phi+om)/2} cos
        g[2] = -csm * sh;  g[3] = -ssm * sh;   // b  = -e^{ i(phi-om)/2} sin
        g[4] =  csm * sh;  g[5] = -ssm * sh;   // c  =  e^{-i(phi-om)/2} sin
        g[6] =  csp * ch;  g[7] =  ssp * ch;   // d  =  e^{ i(phi+om)/2} cos
    }
}

// new_x = a*x + b*y ; new_y = c*x + d*y  (complex)
__device__ __forceinline__ void cgate(float ar, float ai, float br, float bi,
                                      float cr, float ci, float dr, float di,
                                      float2& x, float2& y) {
    float nxr = ar * x.x - ai * x.y + br * y.x - bi * y.y;
    float nxi = ar * x.y + ai * x.x + br * y.y + bi * y.x;
    float nyr = cr * x.x - ci * x.y + dr * y.x - di * y.y;
    float nyi = cr * x.y + ci * x.x + dr * y.y + di * y.x;
    x = make_float2(nxr, nxi);
    y = make_float2(nyr, nyi);
}

__global__ void __launch_bounds__(TPB) vqc_main(
    const float* __restrict__ X,
    const float* __restrict__ W,
    const float* __restrict__ bias,
    float* __restrict__ out)
{
    __shared__ float2 st[DIM];               // state vector (8 KB)
    __shared__ float  gsm[NL * NQ * 8];      // gate coeffs
    __shared__ float  red[(TPB / 32) * NQ];  // cross-warp reduction scratch
    __shared__ float  zsh[NQ];
    __shared__ float  s_invn2;

    int tid = threadIdx.x;
    int b   = blockIdx.x;

    for (int i = tid; i < NL * NQ * 8; i += TPB) gsm[i] = g_gates[i];

    // Load X row (unnormalized real state) + sum of squares
    float4 xv = reinterpret_cast<const float4*>(X + (size_t)b * DIM)[tid];
    st[4 * tid + 0] = make_float2(xv.x, 0.f);
    st[4 * tid + 1] = make_float2(xv.y, 0.f);
    st[4 * tid + 2] = make_float2(xv.z, 0.f);
    st[4 * tid + 3] = make_float2(xv.w, 0.f);
    float ss = xv.x * xv.x + xv.y * xv.y + xv.z * xv.z + xv.w * xv.w;
    #pragma unroll
    for (int o = 16; o > 0; o >>= 1) ss += __shfl_xor_sync(0xffffffffu, ss, o);
    if ((tid & 31) == 0) red[tid >> 5] = ss;
    __syncthreads();
    if (tid == 0) {
        float s = 0.f;
        #pragma unroll
        for (int w = 0; w < TPB / 32; ++w) s += red[w];
        s_invn2 = 1.f / s;                   // read only at the very end
    }

    // ---- circuit: per layer, 5 fused 2-qubit gate passes + 1 permutation ----
    #pragma unroll
    for (int l = 0; l < NL; ++l) {
        #pragma unroll
        for (int g = 0; g < 5; ++g) {
            __syncthreads();
            const float* ga = &gsm[(l * NQ + 2 * g) * 8];      // qubit 2g   (bit bb+1)
            const float* gb = ga + 8;                           // qubit 2g+1 (bit bb)
            int bb   = 8 - 2 * g;
            int low  = tid & ((1 << bb) - 1);
            int base = ((tid >> bb) << (bb + 2)) | low;         // bits bb,bb+1 cleared
            int s1   = 1 << bb;
            float2 v0 = st[base];
            float2 v1 = st[base + s1];
            float2 v2 = st[base + 2 * s1];
            float2 v3 = st[base + 3 * s1];
            // gate on qubit 2g: pairs differing in bit bb+1
            cgate(ga[0], ga[1], ga[2], ga[3], ga[4], ga[5], ga[6], ga[7], v0, v2);
            cgate(ga[0], ga[1], ga[2], ga[3], ga[4], ga[5], ga[6], ga[7], v1, v3);
            // gate on qubit 2g+1: pairs differing in bit bb
            cgate(gb[0], gb[1], gb[2], gb[3], gb[4], gb[5], gb[6], gb[7], v0, v1);
            cgate(gb[0], gb[1], gb[2], gb[3], gb[4], gb[5], gb[6], gb[7], v2, v3);
            st[base]          = v0;
            st[base + s1]     = v1;
            st[base + 2 * s1] = v2;
            st[base + 3 * s1] = v3;
        }
        // CNOT block = basis permutation (gather to regs, sync, scatter)
        __syncthreads();
        float2 tmp[4];
        #pragma unroll
        for (int k = 0; k < 4; ++k) tmp[k] = st[g_perm[l][tid + k * TPB]];
        __syncthreads();
        #pragma unroll
        for (int k = 0; k < 4; ++k) st[tid + k * TPB] = tmp[k];
    }
    __syncthreads();

    // ---- PauliZ expectations (unnormalized) ----
    float z[NQ];
    #pragma unroll
    for (int q = 0; q < NQ; ++q) z[q] = 0.f;
    #pragma unroll
    for (int k = 0; k < 4; ++k) {
        int i = tid + k * TPB;
        float2 v = st[i];
        float p = v.x * v.x + v.y * v.y;
        #pragma unroll
        for (int q = 0; q < NQ; ++q)
            z[q] += ((i >> (NQ - 1 - q)) & 1) ? -p : p;
    }
    #pragma unroll
    for (int q = 0; q < NQ; ++q) {
        #pragma unroll
        for (int o = 16; o > 0; o >>= 1)
            z[q] += __shfl_xor_sync(0xffffffffu, z[q], o);
    }
    if ((tid & 31) == 0) {
        #pragma unroll
        for (int q = 0; q < NQ; ++q) red[(tid >> 5) * NQ + q] = z[q];
    }
    __syncthreads();
    if (tid < NQ) {
        float s = 0.f;
        #pragma unroll
        for (int w = 0; w < TPB / 32; ++w) s += red[w * NQ + tid];
        zsh[tid] = s;
    }
    __syncthreads();

    // ---- linear head: out = (z * invn2) @ W^T + b ----
    if (tid < NOUT) {
        float acc = bias[tid];
        float inv = s_invn2;
        #pragma unroll
        for (int q = 0; q < NQ; ++q) acc += inv * zsh[q] * W[tid * NQ + q];
        out[(size_t)b * NOUT + tid] = acc;
    }
}

extern "C" void kernel_launch(void* const* d_in, const int* in_sizes, int n_in,
                              void* d_out, int out_size) {
    const float* X    = (const float*)d_in[0];   // (BATCH, 1024) f32
    const float* wts  = (const float*)d_in[1];   // (4, 10, 3) f32
    const float* W    = (const float*)d_in[2];   // (16, 10) f32
    const float* bias = (const float*)d_in[3];   // (16,) f32
    float* out = (float*)d_out;                  // (BATCH, 16) f32

    int batch = in_sizes[0] / DIM;
    vqc_init<<<NL, 256>>>(wts);
    vqc_main<<<batch, TPB>>>(X, W, bias, out);
}

// round 4
// speedup vs baseline: 1.4363x; 1.4363x over previous
#include <cuda_runtime.h>

#define NQ   10
#define DIM  1024
#define NL   4
#define NOUT 16
#define TPB  64

typedef unsigned long long ull;

// Scratch (allocation-free rule: __device__ globals)
__device__ ull            g_gates[NL * NQ * 8];   // 40 gates x 8 packed f32x2 coeff pairs
__device__ unsigned short g_perm[NL][DIM];        // per-layer perm, PRE-SWIZZLED values

// Bank-conflict swizzle: bijective on [0,1024)
__device__ __forceinline__ int swz(int i) { return i ^ ((i >> 4) & 15); }

// ---- f32x2 packed helpers ----
__device__ __forceinline__ ull pk(float lo, float hi) {
    ull r; asm("mov.b64 %0, {%1, %2};" : "=l"(r) : "f"(lo), "f"(hi)); return r;
}
__device__ __forceinline__ void upk(ull v, float& lo, float& hi) {
    asm("mov.b64 {%0, %1}, %2;" : "=f"(lo), "=f"(hi) : "l"(v));
}
__device__ __forceinline__ ull mul2(ull a, ull b) {
    ull d; asm("mul.rn.f32x2 %0, %1, %2;" : "=l"(d) : "l"(a), "l"(b)); return d;
}
__device__ __forceinline__ ull fma2(ull a, ull b, ull c) {
    ull d; asm("fma.rn.f32x2 %0, %1, %2, %3;" : "=l"(d) : "l"(a), "l"(b), "l"(c)); return d;
}

// ---------------------------------------------------------------------------
// Init: packed gate coeffs + pre-swizzled CNOT-layer permutation tables.
// Gate packs (sign-baked so swapped operand needs no negate):
//   nx = (ar,ar)(xr,xi) + (-ai,ai)(xi,xr) + (br,br)(yr,yi) + (-bi,bi)(yi,yr)
//   ny = (cr,cr)(xr,xi) + (-ci,ci)(xi,xr) + (dr,dr)(yr,yi) + (-di,di)(yi,yr)
// ---------------------------------------------------------------------------
__global__ void vqc_init(const float* __restrict__ wts) {
    int l = blockIdx.x;
    int r = l % (NQ - 1) + 1;
    for (int j = threadIdx.x; j < DIM; j += blockDim.x) {
        int t = j;
        #pragma unroll
        for (int q = NQ - 1; q >= 0; --q) {
            int pc = NQ - 1 - q;
            int pt = NQ - 1 - ((q + r) % NQ);
            t ^= ((t >> pc) & 1) << pt;
        }
        g_perm[l][j] = (unsigned short)(t ^ ((t >> 4) & 15));  // pre-swizzled
    }
    if (l == 0 && threadIdx.x < NL * NQ) {
        int idx   = threadIdx.x;
        float phi = wts[idx * 3 + 0];
        float th  = wts[idx * 3 + 1];
        float om  = wts[idx * 3 + 2];
        float sh, ch;   sincosf(0.5f * th, &sh, &ch);
        float ssp, csp; sincosf(0.5f * (phi + om), &ssp, &csp);
        float ssm, csm; sincosf(0.5f * (phi - om), &ssm, &csm);
        float ar =  csp * ch, ai = -ssp * ch;   // a = e^{-i(phi+om)/2} cos
        float br = -csm * sh, bi = -ssm * sh;   // b = -e^{ i(phi-om)/2} sin
        float cr =  csm * sh, ci = -ssm * sh;   // c =  e^{-i(phi-om)/2} sin
        float dr =  csp * ch, di =  ssp * ch;   // d =  e^{ i(phi+om)/2} cos
        ull* g = &g_gates[idx * 8];
        g[0] = pk(ar, ar);  g[1] = pk(-ai, ai);
        g[2] = pk(br, br);  g[3] = pk(-bi, bi);
        g[4] = pk(cr, cr);  g[5] = pk(-ci, ci);
        g[6] = pk(dr, dr);  g[7] = pk(-di, di);
    }
}

// Complex 2x2 gate on amplitude pair (x,y): 8 packed FFMA2
__device__ __forceinline__ void cgate2(ull G0, ull G1, ull G2, ull G3,
                                       ull G4, ull G5, ull G6, ull G7,
                                       float2& x, float2& y) {
    ull v  = pk(x.x, x.y), vs = pk(x.y, x.x);
    ull w  = pk(y.x, y.y), ws = pk(y.y, y.x);
    ull nx = mul2(G0, v); nx = fma2(G1, vs, nx); nx = fma2(G2, w, nx); nx = fma2(G3, ws, nx);
    ull ny = mul2(G4, v); ny = fma2(G5, vs, ny); ny = fma2(G6, w, ny); ny = fma2(G7, ws, ny);
    upk(nx, x.x, x.y); upk(ny, y.x, y.y);
}

// Apply gate `gid` to local k-bit m over the 16-amp register tile
#define APPLY_BIT(a, gsm, gid, m)                                              \
    do {                                                                       \
        const ull* _G = &(gsm)[(gid) * 8];                                     \
        ull _G0=_G[0],_G1=_G[1],_G2=_G[2],_G3=_G[3],                           \
            _G4=_G[4],_G5=_G[5],_G6=_G[6],_G7=_G[7];                           \
        _Pragma("unroll")                                                      \
        for (int _p = 0; _p < 8; ++_p) {                                       \
            int _i = ((_p >> (m)) << ((m) + 1)) | (_p & ((1 << (m)) - 1));     \
            cgate2(_G0,_G1,_G2,_G3,_G4,_G5,_G6,_G7, (a)[_i], (a)[_i | (1 << (m))]); \
        }                                                                      \
    } while (0)

__global__ void __launch_bounds__(TPB, 12) vqc_main(
    const float* __restrict__ X,
    const float* __restrict__ W,
    const float* __restrict__ bias,
    float* __restrict__ out)
{
    __shared__ float2 st[DIM];            // state, swizzled layout (8 KB)
    __shared__ ull    gsm[NL * NQ * 8];   // packed gate coeffs (2.5 KB)
    __shared__ float  red2[2];
    __shared__ float  zw[2][NQ];
    __shared__ float  zsh[NQ];
    __shared__ float  s_invn2;

    const int tid = threadIdx.x;
    const int b   = blockIdx.x;
    const int lane = tid & 31, warp = tid >> 5;

    for (int i = tid; i < NL * NQ * 8; i += TPB) gsm[i] = g_gates[i];

    float2 a[16];

    // ---- layer 0, pass 0: read X directly (state real), bits 9..6 = qubits 0..3
    {
        const float* Xr = X + (size_t)b * DIM;
        float ss = 0.f;
        #pragma unroll
        for (int k = 0; k < 16; ++k) {
            float x = Xr[(k << 6) | tid];
            a[k] = make_float2(x, 0.f);
            ss += x * x;
        }
        #pragma unroll
        for (int o = 16; o > 0; o >>= 1) ss += __shfl_xor_sync(0xffffffffu, ss, o);
        if (lane == 0) red2[warp] = ss;
    }
    // gsm is loaded by this block before use: need a sync before reading gsm
    __syncthreads();
    if (tid == 0) s_invn2 = 1.f / (red2[0] + red2[1]);

    APPLY_BIT(a, gsm, 0, 3);   // qubit 0 (bit 9)
    APPLY_BIT(a, gsm, 1, 2);   // qubit 1
    APPLY_BIT(a, gsm, 2, 1);   // qubit 2
    APPLY_BIT(a, gsm, 3, 0);   // qubit 3
    #pragma unroll
    for (int k = 0; k < 16; ++k) st[swz((k << 6) | tid)] = a[k];

    #pragma unroll
    for (int l = 0; l < NL; ++l) {
        const int gb = l * NQ;
        if (l > 0) {
            // pass 0: bits 9..6 (qubits 0..3)
            __syncthreads();
            #pragma unroll
            for (int k = 0; k < 16; ++k) a[k] = st[swz((k << 6) | tid)];
            APPLY_BIT(a, gsm, gb + 0, 3);
            APPLY_BIT(a, gsm, gb + 1, 2);
            APPLY_BIT(a, gsm, gb + 2, 1);
            APPLY_BIT(a, gsm, gb + 3, 0);
            #pragma unroll
            for (int k = 0; k < 16; ++k) st[swz((k << 6) | tid)] = a[k];
        }
        // pass 1: bits 5..2 (qubits 4..7)
        __syncthreads();
        #pragma unroll
        for (int k = 0; k < 16; ++k)
            a[k] = st[swz(((tid >> 2) << 6) | (k << 2) | (tid & 3))];
        APPLY_BIT(a, gsm, gb + 4, 3);
        APPLY_BIT(a, gsm, gb + 5, 2);
        APPLY_BIT(a, gsm, gb + 6, 1);
        APPLY_BIT(a, gsm, gb + 7, 0);
        #pragma unroll
        for (int k = 0; k < 16; ++k)
            st[swz(((tid >> 2) << 6) | (k << 2) | (tid & 3))] = a[k];

        // pass 2: gate bits 1,0 (qubits 8,9); carrier bits 9,8
        __syncthreads();
        #pragma unroll
        for (int k = 0; k < 16; ++k)
            a[k] = st[swz(((k >> 2) << 8) | (tid << 2) | (k & 3))];
        APPLY_BIT(a, gsm, gb + 8, 1);
        APPLY_BIT(a, gsm, gb + 9, 0);
        #pragma unroll
        for (int k = 0; k < 16; ++k)
            st[swz(((k >> 2) << 8) | (tid << 2) | (k & 3))] = a[k];

        if (l < NL - 1) {
            // CNOT-block permutation (layer-3 perm folded into Z phase below)
            __syncthreads();
            #pragma unroll
            for (int k = 0; k < 16; ++k) a[k] = st[g_perm[l][(k << 6) | tid]];
            __syncthreads();
            #pragma unroll
            for (int k = 0; k < 16; ++k) st[swz((k << 6) | tid)] = a[k];
        }
    }
    __syncthreads();

    // ---- PauliZ expectations, reading through layer-3 perm (signs from logical idx)
    float z[NQ];
    #pragma unroll
    for (int q = 0; q < NQ; ++q) z[q] = 0.f;
    #pragma unroll
    for (int k = 0; k < 16; ++k) {
        int j = (k << 6) | tid;                 // logical index
        float2 v = st[g_perm[NL - 1][j]];       // pre-swizzled physical address
        float p = v.x * v.x + v.y * v.y;
        #pragma unroll
        for (int q = 0; q < NQ; ++q)
            z[q] += ((j >> (NQ - 1 - q)) & 1) ? -p : p;
    }
    #pragma unroll
    for (int q = 0; q < NQ; ++q) {
        #pragma unroll
        for (int o = 16; o > 0; o >>= 1)
            z[q] += __shfl_xor_sync(0xffffffffu, z[q], o);
    }
    if (lane == 0) {
        #pragma unroll
        for (int q = 0; q < NQ; ++q) zw[warp][q] = z[q];
    }
    __syncthreads();
    if (tid < NQ) zsh[tid] = zw[0][tid] + zw[1][tid];
    __syncthreads();

    // ---- linear head
    if (tid < NOUT) {
        float acc = bias[tid];
        float inv = s_invn2;
        #pragma unroll
        for (int q = 0; q < NQ; ++q) acc += inv * zsh[q] * W[tid * NQ + q];
        out[(size_t)b * NOUT + tid] = acc;
    }
}

extern "C" void kernel_launch(void* const* d_in, const int* in_sizes, int n_in,
                              void* d_out, int out_size) {
    const float* X    = (const float*)d_in[0];   // (BATCH, 1024) f32
    const float* wts  = (const float*)d_in[1];   // (4, 10, 3) f32
    const float* W    = (const float*)d_in[2];   // (16, 10) f32
    const float* bias = (const float*)d_in[3];   // (16,) f32
    float* out = (float*)d_out;                  // (BATCH, 16) f32

    int batch = in_sizes[0] / DIM;
    vqc_init<<<NL, 256>>>(wts);
    vqc_main<<<batch, TPB>>>(X, W, bias, out);
}

// round 5
// speedup vs baseline: 1.5639x; 1.0889x over previous
#include <cuda_runtime.h>

#define NQ   10
#define DIM  1024
#define NL   4
#define NOUT 16
#define TPB  64

typedef unsigned long long ull;

// Scratch (allocation-free rule: __device__ globals)
__device__ ull            g_gates[NL * NQ * 8];   // 40 gates x 7 broadcast f32x2 packs (+pad)
__device__ unsigned short g_perm[NL][DIM];        // per-layer perm, PRE-SWIZZLED values

// 16B-granule bank swizzle, bijective on [0,1024)
__device__ __forceinline__ int swz4(int i) {
    return i ^ ((i >> 3) & 7) ^ (((i >> 6) & 1) << 2);
}

// ---- f32x2 packed helpers ----
__device__ __forceinline__ ull pk(float lo, float hi) {
    ull r; asm("mov.b64 %0, {%1, %2};" : "=l"(r) : "f"(lo), "f"(hi)); return r;
}
__device__ __forceinline__ void upk(ull v, float& lo, float& hi) {
    asm("mov.b64 {%0, %1}, %2;" : "=f"(lo), "=f"(hi) : "l"(v));
}
__device__ __forceinline__ ull mul2(ull a, ull b) {
    ull d; asm("mul.rn.f32x2 %0, %1, %2;" : "=l"(d) : "l"(a), "l"(b)); return d;
}
__device__ __forceinline__ ull fma2(ull a, ull b, ull c) {
    ull d; asm("fma.rn.f32x2 %0, %1, %2, %3;" : "=l"(d) : "l"(a), "l"(b), "l"(c)); return d;
}
__device__ __forceinline__ ull add2(ull a, ull b) {
    ull d; asm("add.rn.f32x2 %0, %1, %2;" : "=l"(d) : "l"(a), "l"(b)); return d;
}
__device__ __forceinline__ ull neg2(ull a) { return a ^ 0x8000000080000000ULL; }

// ---------------------------------------------------------------------------
// Init: broadcast gate packs + pre-swizzled CNOT-layer permutation tables.
// SU(2): d = conj(a), c = -conj(b)  ->  7 packs per gate:
//   G0=(ar,ar) G1=(ai,ai) G2=(br,br) G3=(bi,bi) G4=(-ai,-ai) G5=(-bi,-bi) G6=(-br,-br)
// ---------------------------------------------------------------------------
__global__ void vqc_init(const float* __restrict__ wts) {
    int l = blockIdx.x;
    int r = l % (NQ - 1) + 1;
    for (int j = threadIdx.x; j < DIM; j += blockDim.x) {
        int t = j;
        #pragma unroll
        for (int q = NQ - 1; q >= 0; --q) {
            int pc = NQ - 1 - q;
            int pt = NQ - 1 - ((q + r) % NQ);
            t ^= ((t >> pc) & 1) << pt;
        }
        g_perm[l][j] = (unsigned short)swz4(t);   // pre-swizzled
    }
    if (l == 0 && threadIdx.x < NL * NQ) {
        int idx   = threadIdx.x;
        float phi = wts[idx * 3 + 0];
        float th  = wts[idx * 3 + 1];
        float om  = wts[idx * 3 + 2];
        float sh, ch;   sincosf(0.5f * th, &sh, &ch);
        float ssp, csp; sincosf(0.5f * (phi + om), &ssp, &csp);
        float ssm, csm; sincosf(0.5f * (phi - om), &ssm, &csm);
        float ar =  csp * ch, ai = -ssp * ch;   // a = e^{-i(phi+om)/2} cos
        float br = -csm * sh, bi = -ssm * sh;   // b = -e^{ i(phi-om)/2} sin
        ull* g = &g_gates[idx * 8];
        g[0] = pk(ar, ar);   g[1] = pk(ai, ai);
        g[2] = pk(br, br);   g[3] = pk(bi, bi);
        g[4] = pk(-ai, -ai); g[5] = pk(-bi, -bi);
        g[6] = pk(-br, -br); g[7] = 0ULL;
    }
}

// Complex 2x2 SU(2) gate on batch-packed pair: 16 FFMA2, no MOVs.
//  nx = a*x + b*y ; ny = -conj(b)*x + conj(a)*y
__device__ __forceinline__ void cgate(ull G0, ull G1, ull G2, ull G3,
                                      ull G4, ull G5, ull G6,
                                      ull& xr, ull& xi, ull& yr, ull& yi) {
    ull oxr = fma2(G5, yi, fma2(G2, yr, fma2(G4, xi, mul2(G0, xr))));
    ull oxi = fma2(G2, yi, fma2(G3, yr, fma2(G0, xi, mul2(G1, xr))));
    ull oyr = fma2(G1, yi, fma2(G0, yr, fma2(G5, xi, mul2(G6, xr))));
    ull oyi = fma2(G0, yi, fma2(G4, yr, fma2(G6, xi, mul2(G3, xr))));
    xr = oxr; xi = oxi; yr = oyr; yi = oyi;
}

// Apply gate `gid` to local k-bit m over the 16-amp register tile
#define APPLY(gid, m)                                                          \
    do {                                                                       \
        const ull* _G = &gsm[(gid) * 8];                                       \
        ull _G0=_G[0],_G1=_G[1],_G2=_G[2],_G3=_G[3],_G4=_G[4],_G5=_G[5],_G6=_G[6]; \
        _Pragma("unroll")                                                      \
        for (int _p = 0; _p < 8; ++_p) {                                       \
            int _i = ((_p >> (m)) << ((m) + 1)) | (_p & ((1 << (m)) - 1));     \
            int _j = _i | (1 << (m));                                          \
            cgate(_G0,_G1,_G2,_G3,_G4,_G5,_G6, re[_i], im[_i], re[_j], im[_j]);\
        }                                                                      \
    } while (0)

__global__ void __launch_bounds__(TPB, 8) vqc_main(
    const float* __restrict__ X,
    const float* __restrict__ W,
    const float* __restrict__ bias,
    float* __restrict__ out)
{
    __shared__ ulonglong2 st[DIM];           // batch-pair state (16 KB), swizzled
    __shared__ ull        gsm[NL * NQ * 8];  // gate packs (2.5 KB)
    __shared__ ull        zw[2][NQ];
    __shared__ ull        zsh[NQ];
    __shared__ float      red2[2][2];
    __shared__ float      s_inv[2];

    const int tid  = threadIdx.x;
    const int b    = blockIdx.x;
    const int lane = tid & 31, warp = tid >> 5;

    for (int i = tid; i < NL * NQ * 8; i += TPB) gsm[i] = g_gates[i];

    ull re[16], im[16];
    const ull zero = pk(0.f, 0.f);

    // ---- load two X rows, packed per-lane; P0 layout (bits 9..6 in regs)
    {
        const float* X0 = X + (size_t)(2 * b) * DIM;
        const float* X1 = X0 + DIM;
        ull ss2 = zero;
        #pragma unroll
        for (int k = 0; k < 16; ++k) {
            int idx = (k << 6) | tid;
            re[k] = pk(X0[idx], X1[idx]);
            im[k] = zero;
            ss2 = fma2(re[k], re[k], ss2);
        }
        float s0, s1; upk(ss2, s0, s1);
        #pragma unroll
        for (int o = 16; o > 0; o >>= 1) {
            s0 += __shfl_xor_sync(0xffffffffu, s0, o);
            s1 += __shfl_xor_sync(0xffffffffu, s1, o);
        }
        if (lane == 0) { red2[warp][0] = s0; red2[warp][1] = s1; }
    }
    __syncthreads();   // gsm + red2 visible
    if (tid == 0) {
        s_inv[0] = 1.f / (red2[0][0] + red2[1][0]);
        s_inv[1] = 1.f / (red2[0][1] + red2[1][1]);
    }

    // ---- layer 0 pass 0 straight from registers
    APPLY(0, 3); APPLY(1, 2); APPLY(2, 1); APPLY(3, 0);
    #pragma unroll
    for (int k = 0; k < 16; ++k)
        st[swz4((k << 6) | tid)] = make_ulonglong2(re[k], im[k]);

    #pragma unroll
    for (int l = 0; l < NL; ++l) {
        const int gb = l * NQ;
        if (l > 0) {
            // pass 0: gather through perm[l-1] (CNOT layer folded), bits 9..6
            __syncthreads();
            #pragma unroll
            for (int k = 0; k < 16; ++k) {
                ulonglong2 v = st[g_perm[l - 1][(k << 6) | tid]];
                re[k] = v.x; im[k] = v.y;
            }
            APPLY(gb + 0, 3); APPLY(gb + 1, 2); APPLY(gb + 2, 1); APPLY(gb + 3, 0);
            __syncthreads();   // all gathers done before overwrite
            #pragma unroll
            for (int k = 0; k < 16; ++k)
                st[swz4((k << 6) | tid)] = make_ulonglong2(re[k], im[k]);
        }
        // pass 1: bits 5..2 (qubits 4..7)
        __syncthreads();
        #pragma unroll
        for (int k = 0; k < 16; ++k) {
            ulonglong2 v = st[swz4(((tid >> 2) << 6) | (k << 2) | (tid & 3))];
            re[k] = v.x; im[k] = v.y;
        }
        APPLY(gb + 4, 3); APPLY(gb + 5, 2); APPLY(gb + 6, 1); APPLY(gb + 7, 0);
        #pragma unroll
        for (int k = 0; k < 16; ++k)
            st[swz4(((tid >> 2) << 6) | (k << 2) | (tid & 3))] = make_ulonglong2(re[k], im[k]);

        // pass 2: bits 1,0 (qubits 8,9); carrier bits 9,8
        __syncthreads();
        #pragma unroll
        for (int k = 0; k < 16; ++k) {
            ulonglong2 v = st[swz4(((k >> 2) << 8) | (tid << 2) | (k & 3))];
            re[k] = v.x; im[k] = v.y;
        }
        APPLY(gb + 8, 1); APPLY(gb + 9, 0);
        #pragma unroll
        for (int k = 0; k < 16; ++k)
            st[swz4(((k >> 2) << 8) | (tid << 2) | (k & 3))] = make_ulonglong2(re[k], im[k]);
    }
    __syncthreads();

    // ---- PauliZ expectations, layer-3 perm folded into gather
    ull p[16];
    #pragma unroll
    for (int k = 0; k < 16; ++k) {
        ulonglong2 v = st[g_perm[NL - 1][(k << 6) | tid]];
        p[k] = fma2(v.y, v.y, mul2(v.x, v.x));
    }
    ull T = p[0];
    #pragma unroll
    for (int k = 1; k < 16; ++k) T = add2(T, p[k]);

    ull z[NQ];
    const ull mtwo = pk(-2.f, -2.f);
    #pragma unroll
    for (int q = 0; q < 4; ++q) {            // qubits 0..3 = local k bits 3..0
        int bit = 3 - q;
        ull S = zero;
        #pragma unroll
        for (int k = 0; k < 16; ++k)
            if ((k >> bit) & 1) S = add2(S, p[k]);
        z[q] = fma2(mtwo, S, T);             // T - 2*S
    }
    ull nT = neg2(T);
    #pragma unroll
    for (int q = 4; q < NQ; ++q)             // qubits 4..9 = tid bits 5..0
        z[q] = ((tid >> (9 - q)) & 1) ? nT : T;

    #pragma unroll
    for (int q = 0; q < NQ; ++q) {
        #pragma unroll
        for (int o = 16; o > 0; o >>= 1)
            z[q] = add2(z[q], __shfl_xor_sync(0xffffffffu, z[q], o));
        if (lane == 0) zw[warp][q] = z[q];
    }
    __syncthreads();
    if (tid < NQ) zsh[tid] = add2(zw[0][tid], zw[1][tid]);
    __syncthreads();

    // ---- linear head: 2 batches x 16 outputs on threads 0..31
    if (tid < 32) {
        int bl = tid >> 4, o = tid & 15;
        float inv = s_inv[bl];
        float acc = bias[o];
        #pragma unroll
        for (int q = 0; q < NQ; ++q) {
            float zl, zh; upk(zsh[q], zl, zh);
            acc += inv * (bl ? zh : zl) * W[o * NQ + q];
        }
        out[(size_t)(2 * b + bl) * NOUT + o] = acc;
    }
}

extern "C" void kernel_launch(void* const* d_in, const int* in_sizes, int n_in,
                              void* d_out, int out_size) {
    const float* X    = (const float*)d_in[0];   // (BATCH, 1024) f32
    const float* wts  = (const float*)d_in[1];   // (4, 10, 3) f32
    const float* W    = (const float*)d_in[2];   // (16, 10) f32
    const float* bias = (const float*)d_in[3];   // (16,) f32
    float* out = (float*)d_out;                  // (BATCH, 16) f32

    int batch = in_sizes[0] / DIM;
    vqc_init<<<NL, 256>>>(wts);
    vqc_main<<<batch / 2, TPB>>>(X, W, bias, out);
}

// round 6
// speedup vs baseline: 1.5993x; 1.0226x over previous
#include <cuda_runtime.h>

#define NQ   10
#define DIM  1024
#define NL   4
#define NOUT 16
#define TPB  128

typedef unsigned long long ull;

// Scratch (allocation-free rule: __device__ globals)
__device__ ull            g_gates[NL * NQ * 8];   // 40 gates x 7 broadcast f32x2 packs (+pad)
__device__ unsigned short g_perm[NL][DIM];        // per-layer perm, PRE-SWIZZLED values

// 16B-granule bank swizzle, bijective on [0,1024); keeps bit 0 intact.
__device__ __forceinline__ int swz(int i) { return i ^ (((i >> 4) & 7) << 1); }

// ---- f32x2 packed helpers ----
__device__ __forceinline__ ull pk(float lo, float hi) {
    ull r; asm("mov.b64 %0, {%1, %2};" : "=l"(r) : "f"(lo), "f"(hi)); return r;
}
__device__ __forceinline__ void upk(ull v, float& lo, float& hi) {
    asm("mov.b64 {%0, %1}, %2;" : "=f"(lo), "=f"(hi) : "l"(v));
}
__device__ __forceinline__ ull mul2(ull a, ull b) {
    ull d; asm("mul.rn.f32x2 %0, %1, %2;" : "=l"(d) : "l"(a), "l"(b)); return d;
}
__device__ __forceinline__ ull fma2(ull a, ull b, ull c) {
    ull d; asm("fma.rn.f32x2 %0, %1, %2, %3;" : "=l"(d) : "l"(a), "l"(b), "l"(c)); return d;
}
__device__ __forceinline__ ull add2(ull a, ull b) {
    ull d; asm("add.rn.f32x2 %0, %1, %2;" : "=l"(d) : "l"(a), "l"(b)); return d;
}
__device__ __forceinline__ ull neg2(ull a) { return a ^ 0x8000000080000000ULL; }

// ---------------------------------------------------------------------------
// Init: broadcast gate packs + pre-swizzled CNOT-layer permutation tables.
// SU(2): d = conj(a), c = -conj(b)  ->  7 packs per gate:
//   G0=(ar) G1=(ai) G2=(br) G3=(bi) G4=(-ai) G5=(-bi) G6=(-br)
// ---------------------------------------------------------------------------
__global__ void vqc_init(const float* __restrict__ wts) {
    int l = blockIdx.x;
    int r = l % (NQ - 1) + 1;
    for (int j = threadIdx.x; j < DIM; j += blockDim.x) {
        int t = j;
        #pragma unroll
        for (int q = NQ - 1; q >= 0; --q) {
            int pc = NQ - 1 - q;
            int pt = NQ - 1 - ((q + r) % NQ);
            t ^= ((t >> pc) & 1) << pt;
        }
        g_perm[l][j] = (unsigned short)swz(t);   // pre-swizzled
    }
    if (l == 0 && threadIdx.x < NL * NQ) {
        int idx   = threadIdx.x;
        float phi = wts[idx * 3 + 0];
        float th  = wts[idx * 3 + 1];
        float om  = wts[idx * 3 + 2];
        float sh, ch;   sincosf(0.5f * th, &sh, &ch);
        float ssp, csp; sincosf(0.5f * (phi + om), &ssp, &csp);
        float ssm, csm; sincosf(0.5f * (phi - om), &ssm, &csm);
        float ar =  csp * ch, ai = -ssp * ch;   // a = e^{-i(phi+om)/2} cos
        float br = -csm * sh, bi = -ssm * sh;   // b = -e^{ i(phi-om)/2} sin
        ull* g = &g_gates[idx * 8];
        g[0] = pk(ar, ar);   g[1] = pk(ai, ai);
        g[2] = pk(br, br);   g[3] = pk(bi, bi);
        g[4] = pk(-ai, -ai); g[5] = pk(-bi, -bi);
        g[6] = pk(-br, -br); g[7] = 0ULL;
    }
}

// Complex 2x2 SU(2) gate on batch-packed pair: 16 FFMA2, no MOVs.
__device__ __forceinline__ void cgate(ull G0, ull G1, ull G2, ull G3,
                                      ull G4, ull G5, ull G6,
                                      ull& xr, ull& xi, ull& yr, ull& yi) {
    ull oxr = fma2(G5, yi, fma2(G2, yr, fma2(G4, xi, mul2(G0, xr))));
    ull oxi = fma2(G2, yi, fma2(G3, yr, fma2(G0, xi, mul2(G1, xr))));
    ull oyr = fma2(G1, yi, fma2(G0, yr, fma2(G5, xi, mul2(G6, xr))));
    ull oyi = fma2(G0, yi, fma2(G4, yr, fma2(G6, xi, mul2(G3, xr))));
    xr = oxr; xi = oxi; yr = oyr; yi = oyi;
}

// Apply gate `gid` to local k-bit m over the 8-amp register tile
#define APPLY(gid, m)                                                          \
    do {                                                                       \
        const ull* _G = &gsm[(gid) * 8];                                       \
        ull _G0=_G[0],_G1=_G[1],_G2=_G[2],_G3=_G[3],_G4=_G[4],_G5=_G[5],_G6=_G[6]; \
        _Pragma("unroll")                                                      \
        for (int _p = 0; _p < 4; ++_p) {                                       \
            int _i = ((_p >> (m)) << ((m) + 1)) | (_p & ((1 << (m)) - 1));     \
            int _j = _i | (1 << (m));                                          \
            cgate(_G0,_G1,_G2,_G3,_G4,_G5,_G6, re[_i], im[_i], re[_j], im[_j]);\
        }                                                                      \
    } while (0)

// Gate on lane bit 0 (qubit 9) via warp shuffle; each thread computes its half.
#define APPLY_SHFL(gid)                                                        \
    do {                                                                       \
        const ull* _G = &gsm[(gid) * 8];                                       \
        int _s = tid & 1;                                                      \
        ull _c1r = _G[0];                                                      \
        ull _c1i = _s ? _G[4] : _G[1];                                         \
        ull _n1i = _s ? _G[1] : _G[4];                                         \
        ull _c2r = _s ? _G[6] : _G[2];                                         \
        ull _c2i = _G[3], _n2i = _G[5];                                        \
        _Pragma("unroll")                                                      \
        for (int _k = 0; _k < 8; ++_k) {                                       \
            ull _vr = re[_k], _vi = im[_k];                                    \
            ull _ur = __shfl_xor_sync(0xffffffffu, _vr, 1);                    \
            ull _ui = __shfl_xor_sync(0xffffffffu, _vi, 1);                    \
            re[_k] = fma2(_n2i,_ui, fma2(_c2r,_ur, fma2(_n1i,_vi, mul2(_c1r,_vr)))); \
            im[_k] = fma2(_c2i,_ur, fma2(_c2r,_ui, fma2(_c1i,_vr, mul2(_c1r,_vi)))); \
        }                                                                      \
    } while (0)

__global__ void __launch_bounds__(TPB, 6) vqc_main(
    const float* __restrict__ X,
    const float* __restrict__ W,
    const float* __restrict__ bias,
    float* __restrict__ out)
{
    __shared__ ulonglong2 st[DIM];           // batch-pair state (16 KB), swizzled
    __shared__ ull        gsm[NL * NQ * 8];  // gate packs (2.5 KB)
    __shared__ ull        zw[4][NQ];
    __shared__ ull        zsh[NQ];
    __shared__ float      red2[4][2];
    __shared__ float      s_inv[2];

    const int tid  = threadIdx.x;
    const int b    = blockIdx.x;
    const int lane = tid & 31, warp = tid >> 5;

    for (int i = tid; i < NL * NQ * 8; i += TPB) gsm[i] = g_gates[i];

    ull re[8], im[8];
    const ull zero = pk(0.f, 0.f);

    // ---- load two X rows in pattern A (bits 9..7 = k), coalesced
    {
        const float* X0 = X + (size_t)(2 * b) * DIM;
        const float* X1 = X0 + DIM;
        ull ss2 = zero;
        #pragma unroll
        for (int k = 0; k < 8; ++k) {
            int idx = (k << 7) | tid;
            re[k] = pk(X0[idx], X1[idx]);
            im[k] = zero;
            ss2 = fma2(re[k], re[k], ss2);
        }
        float s0, s1; upk(ss2, s0, s1);
        #pragma unroll
        for (int o = 16; o > 0; o >>= 1) {
            s0 += __shfl_xor_sync(0xffffffffu, s0, o);
            s1 += __shfl_xor_sync(0xffffffffu, s1, o);
        }
        if (lane == 0) { red2[warp][0] = s0; red2[warp][1] = s1; }
    }
    __syncthreads();   // gsm + red2 visible
    if (tid == 0) {
        s_inv[0] = 1.f / (red2[0][0] + red2[1][0] + red2[2][0] + red2[3][0]);
        s_inv[1] = 1.f / (red2[0][1] + red2[1][1] + red2[2][1] + red2[3][1]);
    }

    #pragma unroll
    for (int l = 0; l < NL; ++l) {
        const int gb = l * NQ;
        // ---- round A: qubits 0..2 (bits 9..7 = k)
        if (l == 0) {
            // registers already hold pattern A straight from X
            APPLY(gb + 0, 2); APPLY(gb + 1, 1); APPLY(gb + 2, 0);
            #pragma unroll
            for (int k = 0; k < 8; ++k)
                st[swz((k << 7) | tid)] = make_ulonglong2(re[k], im[k]);
        } else {
            __syncthreads();          // prev layer's round-C stores visible
            #pragma unroll
            for (int k = 0; k < 8; ++k) {
                ulonglong2 v = st[g_perm[l - 1][(k << 7) | tid]];  // CNOT folded
                re[k] = v.x; im[k] = v.y;
            }
            APPLY(gb + 0, 2); APPLY(gb + 1, 1); APPLY(gb + 2, 0);
            __syncthreads();          // all gathers done before overwrite
            #pragma unroll
            for (int k = 0; k < 8; ++k)
                st[swz((k << 7) | tid)] = make_ulonglong2(re[k], im[k]);
        }
        // ---- round B: qubits 3..5 (bits 6..4 = k)
        __syncthreads();
        #pragma unroll
        for (int k = 0; k < 8; ++k) {
            ulonglong2 v = st[swz(((tid >> 4) << 7) | (k << 4) | (tid & 15))];
            re[k] = v.x; im[k] = v.y;
        }
        APPLY(gb + 3, 2); APPLY(gb + 4, 1); APPLY(gb + 5, 0);
        #pragma unroll
        for (int k = 0; k < 8; ++k)
            st[swz(((tid >> 4) << 7) | (k << 4) | (tid & 15))] = make_ulonglong2(re[k], im[k]);

        // ---- round C: qubits 6..8 (bits 3..1 = k), qubit 9 (bit 0) via shfl
        __syncthreads();
        #pragma unroll
        for (int k = 0; k < 8; ++k) {
            ulonglong2 v = st[swz(((tid >> 1) << 4) | (k << 1) | (tid & 1))];
            re[k] = v.x; im[k] = v.y;
        }
        APPLY(gb + 6, 2); APPLY(gb + 7, 1); APPLY(gb + 8, 0);
        APPLY_SHFL(gb + 9);
        #pragma unroll
        for (int k = 0; k < 8; ++k)
            st[swz(((tid >> 1) << 4) | (k << 1) | (tid & 1))] = make_ulonglong2(re[k], im[k]);
    }
    __syncthreads();

    // ---- PauliZ expectations; layer-3 perm folded into gather (pattern A)
    ull p[8];
    #pragma unroll
    for (int k = 0; k < 8; ++k) {
        ulonglong2 v = st[g_perm[NL - 1][(k << 7) | tid]];
        p[k] = fma2(v.y, v.y, mul2(v.x, v.x));
    }
    ull T = p[0];
    #pragma unroll
    for (int k = 1; k < 8; ++k) T = add2(T, p[k]);

    ull z[NQ];
    const ull mtwo = pk(-2.f, -2.f);
    #pragma unroll
    for (int q = 0; q < 3; ++q) {            // qubits 0..2 = k bits 2..0
        int bit = 2 - q;
        ull S = zero;
        #pragma unroll
        for (int k = 0; k < 8; ++k)
            if ((k >> bit) & 1) S = add2(S, p[k]);
        z[q] = fma2(mtwo, S, T);             // T - 2*S
    }
    ull nT = neg2(T);
    #pragma unroll
    for (int q = 3; q < NQ; ++q)             // qubits 3..9 = tid bits 6..0
        z[q] = ((tid >> (9 - q)) & 1) ? nT : T;

    #pragma unroll
    for (int q = 0; q < NQ; ++q) {
        #pragma unroll
        for (int o = 16; o > 0; o >>= 1)
            z[q] = add2(z[q], __shfl_xor_sync(0xffffffffu, z[q], o));
        if (lane == 0) zw[warp][q] = z[q];
    }
    __syncthreads();
    if (tid < NQ)
        zsh[tid] = add2(add2(zw[0][tid], zw[1][tid]), add2(zw[2][tid], zw[3][tid]));
    __syncthreads();

    // ---- linear head: 2 batches x 16 outputs on threads 0..31
    if (tid < 32) {
        int bl = tid >> 4, o = tid & 15;
        float inv = s_inv[bl];
        float acc = bias[o];
        #pragma unroll
        for (int q = 0; q < NQ; ++q) {
            float zl, zh; upk(zsh[q], zl, zh);
            acc += inv * (bl ? zh : zl) * W[o * NQ + q];
        }
        out[(size_t)(2 * b + bl) * NOUT + o] = acc;
    }
}

extern "C" void kernel_launch(void* const* d_in, const int* in_sizes, int n_in,
                              void* d_out, int out_size) {
    const float* X    = (const float*)d_in[0];   // (BATCH, 1024) f32
    const float* wts  = (const float*)d_in[1];   // (4, 10, 3) f32
    const float* W    = (const float*)d_in[2];   // (16, 10) f32
    const float* bias = (const float*)d_in[3];   // (16,) f32
    float* out = (float*)d_out;                  // (BATCH, 16) f32

    int batch = in_sizes[0] / DIM;
    vqc_init<<<NL, 256>>>(wts);
    vqc_main<<<batch / 2, TPB>>>(X, W, bias, out);
}